// round 2
// baseline (speedup 1.0000x reference)
#include <cuda_runtime.h>
#include <cuda_bf16.h>
#include <math.h>

#define NN 50000
#define EE 1600000
#define IND 256
#define OUTD 64
#define NH 4

// ---------------- scratch (static device arrays; zero-initialized) ----------
__device__ float  g_x[NN * OUTD];          // 12.8 MB  x = h@W
__device__ float4 g_el[NN];                // el per node (4 heads)
__device__ float4 g_er[NN];                // er per node
__device__ int    g_deg[NN];               // invariant: zero at kernel_launch entry
__device__ int    g_off[NN + 1];
__device__ int    g_cur[NN];
__device__ int    g_dst_s[EE];             // CSR-sorted dst

// ---------------- helpers ----------------------------------------------------
__device__ __forceinline__ float lrelu_exp(float v)
{
    float t = (v >= 0.f) ? v : 0.2f * v;
    return expf(t);
}
__device__ __forceinline__ float elu1(float v)
{
    return (v > 0.f) ? v : expm1f(v);
}

// ---------------- K1: fused [x = h@W]  ||  [degree histogram] ---------------
__global__ void k_fused1(const float* __restrict__ h, const float* __restrict__ W,
                         const int* __restrict__ ei, int N, int E, int gemm_blocks)
{
    __shared__ float  As[128 * 36];     // padded stride 36
    __shared__ float4 Bs[32 * 16];      // 32 k x 64 n as float4

    if (blockIdx.x >= gemm_blocks) {
        // ---- degree histogram path (atomic-bound, hides under gemm) ----
        int nb  = gridDim.x - gemm_blocks;
        int bid = blockIdx.x - gemm_blocks;
        int stride = nb * blockDim.x;
        if ((E & 3) == 0) {
            const int4* e4 = (const int4*)ei;
            int E4 = E >> 2;
            for (int i = bid * blockDim.x + threadIdx.x; i < E4; i += stride) {
                int4 v = e4[i];
                atomicAdd(&g_deg[v.x], 1);
                atomicAdd(&g_deg[v.y], 1);
                atomicAdd(&g_deg[v.z], 1);
                atomicAdd(&g_deg[v.w], 1);
            }
        } else {
            for (int e = bid * blockDim.x + threadIdx.x; e < E; e += stride)
                atomicAdd(&g_deg[ei[e]], 1);
        }
        return;
    }

    // ---- GEMM path: 128x64 tile, 256 threads, 8x4 microtile ----
    const int tid = threadIdx.x;
    const int m0  = blockIdx.x * 128;
    const int tx  = tid & 15;
    const int ty  = tid >> 4;

    float acc[8][4];
#pragma unroll
    for (int i = 0; i < 8; i++)
#pragma unroll
        for (int j = 0; j < 4; j++) acc[i][j] = 0.f;

    for (int k0 = 0; k0 < IND; k0 += 32) {
#pragma unroll
        for (int l = 0; l < 4; l++) {
            int f   = tid + 256 * l;
            int row = f >> 3;
            int kq  = f & 7;
            int gm  = m0 + row;
            float4 v = make_float4(0.f, 0.f, 0.f, 0.f);
            if (gm < N) v = *(const float4*)(h + (size_t)gm * IND + k0 + kq * 4);
            *(float4*)(As + row * 36 + kq * 4) = v;
        }
#pragma unroll
        for (int l = 0; l < 2; l++) {
            int f  = tid + 256 * l;
            int kk = f >> 4;
            int nq = f & 15;
            Bs[kk * 16 + nq] = *(const float4*)(W + (size_t)(k0 + kk) * OUTD + nq * 4);
        }
        __syncthreads();

#pragma unroll
        for (int k = 0; k < 32; k++) {
            float4 bv = Bs[k * 16 + tx];
#pragma unroll
            for (int i = 0; i < 8; i++) {
                float a = As[(ty * 8 + i) * 36 + k];
                acc[i][0] += a * bv.x;
                acc[i][1] += a * bv.y;
                acc[i][2] += a * bv.z;
                acc[i][3] += a * bv.w;
            }
        }
        __syncthreads();
    }

#pragma unroll
    for (int i = 0; i < 8; i++) {
        int gm = m0 + ty * 8 + i;
        if (gm < N) {
            float4 v = make_float4(acc[i][0], acc[i][1], acc[i][2], acc[i][3]);
            *(float4*)(g_x + (size_t)gm * OUTD + tx * 4) = v;
        }
    }
}

// ---------------- K2: fast exclusive scan + deg re-zero ----------------------
// 1024 threads, each serially owns ceil(N/1024) elements. One block scan.
__global__ void k_scan(int N)
{
    __shared__ int sm[1024];
    const int t  = threadIdx.x;
    const int CH = (N + 1023) / 1024;
    int beg = t * CH;
    int end = beg + CH; if (end > N) end = N;

    int s = 0;
    for (int i = beg; i < end; i++) s += g_deg[i];
    sm[t] = s;
    __syncthreads();
#pragma unroll
    for (int o = 1; o < 1024; o <<= 1) {
        int v = (t >= o) ? sm[t - o] : 0;
        __syncthreads();
        sm[t] += v;
        __syncthreads();
    }
    int run = sm[t] - s;   // exclusive prefix
    for (int i = beg; i < end; i++) {
        int dv = g_deg[i];
        g_off[i] = run;
        g_cur[i] = run;
        g_deg[i] = 0;      // restore invariant for next graph replay
        run += dv;
    }
    if (t == 1023) g_off[N] = sm[1023];
}

// ---------------- K3: fused [el/er projections] || [CSR scatter (dst only)] --
__global__ void k_fused3(const float* __restrict__ Wl, const float* __restrict__ Wr,
                         const int* __restrict__ ei, int N, int E, int elr_blocks)
{
    if (blockIdx.x < elr_blocks) {
        // ---- el/er: warp per node ----
        int warp = (blockIdx.x * blockDim.x + threadIdx.x) >> 5;
        int lane = threadIdx.x & 31;
        if (warp >= N) return;

        const float* xr = g_x + (size_t)warp * OUTD;
        float x0 = xr[lane];
        float x1 = xr[lane + 32];

        float s[8];
#pragma unroll
        for (int hd = 0; hd < NH; hd++) {
            s[hd]     = x0 * __ldg(Wl + hd * OUTD + lane) + x1 * __ldg(Wl + hd * OUTD + lane + 32);
            s[4 + hd] = x0 * __ldg(Wr + hd * OUTD + lane) + x1 * __ldg(Wr + hd * OUTD + lane + 32);
        }
#pragma unroll
        for (int o = 16; o > 0; o >>= 1) {
#pragma unroll
            for (int j = 0; j < 8; j++) s[j] += __shfl_xor_sync(0xffffffffu, s[j], o);
        }
        if (lane == 0) {
            g_el[warp] = make_float4(s[0], s[1], s[2], s[3]);
            g_er[warp] = make_float4(s[4], s[5], s[6], s[7]);
        }
    } else {
        // ---- scatter: bucket edge dst by src (no attention value stored) ----
        int e = (blockIdx.x - elr_blocks) * blockDim.x + threadIdx.x;
        if (e >= E) return;
        int sN = ei[e];
        int d  = ei[E + e];
        int pos = atomicAdd(&g_cur[sN], 1);
        g_dst_s[pos] = d;
    }
}

// ---------------- K4: per-node aggregation, attention computed on the fly ---
__global__ void k_agg(const float* __restrict__ b, float* __restrict__ out, int N)
{
    int warp = (blockIdx.x * blockDim.x + threadIdx.x) >> 5;
    int lane = threadIdx.x & 31;
    if (warp >= N) return;

    int s0 = g_off[warp];
    int s1 = g_off[warp + 1];
    float4 el = g_el[warp];

    float a00 = 0.f, a01 = 0.f, a10 = 0.f, a11 = 0.f;
    float a20 = 0.f, a21 = 0.f, a30 = 0.f, a31 = 0.f;
    float e0 = 0.f, e1 = 0.f, e2 = 0.f, e3 = 0.f;

    for (int c = s0; c < s1; c += 32) {
        int rem = s1 - c;
        int n = rem < 32 ? rem : 32;

        // each lane computes attention for one edge of the chunk (parallel exps)
        int   dL = 0;
        float ex_ = 0.f, ey_ = 0.f, ez_ = 0.f, ew_ = 0.f;
        if (lane < n) {
            dL = g_dst_s[c + lane];
            float4 er = g_er[dL];
            ex_ = lrelu_exp(el.x + er.x);
            ey_ = lrelu_exp(el.y + er.y);
            ez_ = lrelu_exp(el.z + er.z);
            ew_ = lrelu_exp(el.w + er.w);
        }

#pragma unroll 2
        for (int j = 0; j < n; j++) {
            int   dj = __shfl_sync(0xffffffffu, dL, j);
            float ex = __shfl_sync(0xffffffffu, ex_, j);
            float ey = __shfl_sync(0xffffffffu, ey_, j);
            float ez = __shfl_sync(0xffffffffu, ez_, j);
            float ew = __shfl_sync(0xffffffffu, ew_, j);
            const float* xr = g_x + (size_t)dj * OUTD;
            float x0 = xr[lane];
            float x1 = xr[lane + 32];
            a00 += ex * x0;  a01 += ex * x1;
            a10 += ey * x0;  a11 += ey * x1;
            a20 += ez * x0;  a21 += ez * x1;
            a30 += ew * x0;  a31 += ew * x1;
            e0 += ex; e1 += ey; e2 += ez; e3 += ew;
        }
    }

    float i0 = 1.f / fmaxf(e0, 1e-12f);
    float i1 = 1.f / fmaxf(e1, 1e-12f);
    float i2 = 1.f / fmaxf(e2, 1e-12f);
    float i3 = 1.f / fmaxf(e3, 1e-12f);

    float b0 = __ldg(b + lane);
    float b1 = __ldg(b + lane + 32);

    float* o = out + (size_t)warp * (NH * OUTD);
    o[0 * OUTD + lane]      = elu1(a00 * i0 + b0);
    o[0 * OUTD + lane + 32] = elu1(a01 * i0 + b1);
    o[1 * OUTD + lane]      = elu1(a10 * i1 + b0);
    o[1 * OUTD + lane + 32] = elu1(a11 * i1 + b1);
    o[2 * OUTD + lane]      = elu1(a20 * i2 + b0);
    o[2 * OUTD + lane + 32] = elu1(a21 * i2 + b1);
    o[3 * OUTD + lane]      = elu1(a30 * i3 + b0);
    o[3 * OUTD + lane + 32] = elu1(a31 * i3 + b1);
}

// ---------------- launch -----------------------------------------------------
extern "C" void kernel_launch(void* const* d_in, const int* in_sizes, int n_in,
                              void* d_out, int out_size)
{
    const float* h  = (const float*)d_in[0];   // [N, 256]
    const float* W  = (const float*)d_in[1];   // [256, 64]
    const float* Wl = (const float*)d_in[2];   // [4, 64]
    const float* Wr = (const float*)d_in[3];   // [4, 64]
    const float* b  = (const float*)d_in[4];   // [64]
    const int*   ei = (const int*)d_in[5];     // [2, E]
    float* out = (float*)d_out;

    int N = in_sizes[0] / IND;
    int E = in_sizes[5] / 2;

    int GB = (N + 127) / 128;
    int DEG_BLOCKS = 1024;
    k_fused1<<<GB + DEG_BLOCKS, 256>>>(h, W, ei, N, E, GB);

    k_scan<<<1, 1024>>>(N);

    int EB = (N + 7) / 8;            // elr blocks (warp per node)
    int SB = (E + 255) / 256;        // scatter blocks
    k_fused3<<<EB + SB, 256>>>(Wl, Wr, ei, N, E, EB);

    k_agg<<<(N + 7) / 8, 256>>>(b, out, N);
}

// round 3
// speedup vs baseline: 1.0976x; 1.0976x over previous
#include <cuda_runtime.h>
#include <cuda_bf16.h>
#include <math.h>

#define NN 50000
#define EE 1600000
#define IND 256
#define OUTD 64
#define NH 4

// ---------------- scratch (static device arrays; zero-initialized) ----------
__device__ float  g_x[NN * OUTD];          // 12.8 MB  x = h@W
__device__ float4 g_el[NN];                // el per node (4 heads)
__device__ float4 g_er[NN];                // er per node
__device__ int    g_deg[NN];               // invariant: zero at kernel_launch entry
__device__ int    g_off[NN + 1];
__device__ int    g_cur[NN];
__device__ int    g_dst_s[EE];             // CSR-sorted dst

// ---------------- helpers ----------------------------------------------------
__device__ __forceinline__ float lrelu_exp(float v)
{
    float t = (v >= 0.f) ? v : 0.2f * v;
    return __expf(t);
}
__device__ __forceinline__ float elu1(float v)
{
    return (v > 0.f) ? v : expm1f(v);
}

// ---------------- K1: fused [x = h@W]  ||  [degree histogram] ---------------
__global__ void k_fused1(const float* __restrict__ h, const float* __restrict__ W,
                         const int* __restrict__ ei, int N, int E, int gemm_blocks)
{
    __shared__ float  As[128 * 36];     // padded stride 36
    __shared__ float4 Bs[32 * 16];      // 32 k x 64 n as float4

    if (blockIdx.x >= gemm_blocks) {
        // ---- degree histogram path (atomic-bound, hides under gemm) ----
        int nb  = gridDim.x - gemm_blocks;
        int bid = blockIdx.x - gemm_blocks;
        int stride = nb * blockDim.x;
        if ((E & 3) == 0) {
            const int4* e4 = (const int4*)ei;
            int E4 = E >> 2;
            for (int i = bid * blockDim.x + threadIdx.x; i < E4; i += stride) {
                int4 v = e4[i];
                atomicAdd(&g_deg[v.x], 1);
                atomicAdd(&g_deg[v.y], 1);
                atomicAdd(&g_deg[v.z], 1);
                atomicAdd(&g_deg[v.w], 1);
            }
        } else {
            for (int e = bid * blockDim.x + threadIdx.x; e < E; e += stride)
                atomicAdd(&g_deg[ei[e]], 1);
        }
        return;
    }

    // ---- GEMM path: 128x64 tile, 256 threads, 8x4 microtile ----
    const int tid = threadIdx.x;
    const int m0  = blockIdx.x * 128;
    const int tx  = tid & 15;
    const int ty  = tid >> 4;

    float acc[8][4];
#pragma unroll
    for (int i = 0; i < 8; i++)
#pragma unroll
        for (int j = 0; j < 4; j++) acc[i][j] = 0.f;

    for (int k0 = 0; k0 < IND; k0 += 32) {
#pragma unroll
        for (int l = 0; l < 4; l++) {
            int f   = tid + 256 * l;
            int row = f >> 3;
            int kq  = f & 7;
            int gm  = m0 + row;
            float4 v = make_float4(0.f, 0.f, 0.f, 0.f);
            if (gm < N) v = *(const float4*)(h + (size_t)gm * IND + k0 + kq * 4);
            *(float4*)(As + row * 36 + kq * 4) = v;
        }
#pragma unroll
        for (int l = 0; l < 2; l++) {
            int f  = tid + 256 * l;
            int kk = f >> 4;
            int nq = f & 15;
            Bs[kk * 16 + nq] = *(const float4*)(W + (size_t)(k0 + kk) * OUTD + nq * 4);
        }
        __syncthreads();

#pragma unroll
        for (int k = 0; k < 32; k++) {
            float4 bv = Bs[k * 16 + tx];
#pragma unroll
            for (int i = 0; i < 8; i++) {
                float a = As[(ty * 8 + i) * 36 + k];
                acc[i][0] += a * bv.x;
                acc[i][1] += a * bv.y;
                acc[i][2] += a * bv.z;
                acc[i][3] += a * bv.w;
            }
        }
        __syncthreads();
    }

#pragma unroll
    for (int i = 0; i < 8; i++) {
        int gm = m0 + ty * 8 + i;
        if (gm < N) {
            float4 v = make_float4(acc[i][0], acc[i][1], acc[i][2], acc[i][3]);
            *(float4*)(g_x + (size_t)gm * OUTD + tx * 4) = v;
        }
    }
}

// ---------------- K2: fast exclusive scan + deg re-zero ----------------------
__global__ void k_scan(int N)
{
    __shared__ int sm[1024];
    const int t  = threadIdx.x;
    const int CH = (N + 1023) / 1024;
    int beg = t * CH;
    int end = beg + CH; if (end > N) end = N;

    int s = 0;
    for (int i = beg; i < end; i++) s += g_deg[i];
    sm[t] = s;
    __syncthreads();
#pragma unroll
    for (int o = 1; o < 1024; o <<= 1) {
        int v = (t >= o) ? sm[t - o] : 0;
        __syncthreads();
        sm[t] += v;
        __syncthreads();
    }
    int run = sm[t] - s;   // exclusive prefix
    for (int i = beg; i < end; i++) {
        int dv = g_deg[i];
        g_off[i] = run;
        g_cur[i] = run;
        g_deg[i] = 0;      // restore invariant for next graph replay
        run += dv;
    }
    if (t == 1023) g_off[N] = sm[1023];
}

// ---------------- K3: fused [el/er projections] || [CSR scatter (dst only)] --
__global__ void k_fused3(const float* __restrict__ Wl, const float* __restrict__ Wr,
                         const int* __restrict__ ei, int N, int E, int elr_blocks)
{
    if (blockIdx.x < elr_blocks) {
        int warp = (blockIdx.x * blockDim.x + threadIdx.x) >> 5;
        int lane = threadIdx.x & 31;
        if (warp >= N) return;

        const float* xr = g_x + (size_t)warp * OUTD;
        float x0 = xr[lane];
        float x1 = xr[lane + 32];

        float s[8];
#pragma unroll
        for (int hd = 0; hd < NH; hd++) {
            s[hd]     = x0 * __ldg(Wl + hd * OUTD + lane) + x1 * __ldg(Wl + hd * OUTD + lane + 32);
            s[4 + hd] = x0 * __ldg(Wr + hd * OUTD + lane) + x1 * __ldg(Wr + hd * OUTD + lane + 32);
        }
#pragma unroll
        for (int o = 16; o > 0; o >>= 1) {
#pragma unroll
            for (int j = 0; j < 8; j++) s[j] += __shfl_xor_sync(0xffffffffu, s[j], o);
        }
        if (lane == 0) {
            g_el[warp] = make_float4(s[0], s[1], s[2], s[3]);
            g_er[warp] = make_float4(s[4], s[5], s[6], s[7]);
        }
    } else {
        int e = (blockIdx.x - elr_blocks) * blockDim.x + threadIdx.x;
        if (e >= E) return;
        int sN = ei[e];
        int d  = ei[E + e];
        int pos = atomicAdd(&g_cur[sN], 1);
        g_dst_s[pos] = d;
    }
}

// ---------------- K4: per-node aggregation, smem-staged + f32x2 inner loop --
union U64 { unsigned long long u; float2 f; };

__global__ void k_agg(const float* __restrict__ b, float* __restrict__ out, int N)
{
    __shared__ int    s_off[8][32];
    __shared__ float4 s_e[8][32][2];    // duplicated packed: (ex,ex,ey,ey),(ez,ez,ew,ew)

    const int w    = threadIdx.x >> 5;
    const int lane = threadIdx.x & 31;
    const int node = blockIdx.x * 8 + w;
    if (node >= N) return;

    const int s0 = g_off[node];
    const int s1 = g_off[node + 1];
    const float4 el = g_el[node];

    unsigned long long a0 = 0ull, a1 = 0ull, a2 = 0ull, a3 = 0ull; // (0.f,0.f) packed
    float e0 = 0.f, e1 = 0.f, e2 = 0.f, e3 = 0.f;

    const float* xl = g_x + lane * 2;   // lane owns dims {2*lane, 2*lane+1}

    for (int c = s0; c < s1; c += 32) {
        int rem = s1 - c;
        int n = rem < 32 ? rem : 32;

        // ---- stage: lane-parallel attention computation ----
        if (lane < n) {
            int d = g_dst_s[c + lane];
            float4 er = g_er[d];
            float ex = lrelu_exp(el.x + er.x);
            float ey = lrelu_exp(el.y + er.y);
            float ez = lrelu_exp(el.z + er.z);
            float ew = lrelu_exp(el.w + er.w);
            e0 += ex; e1 += ey; e2 += ez; e3 += ew;      // lane-local rowsum
            s_off[w][lane]  = d * OUTD;
            s_e[w][lane][0] = make_float4(ex, ex, ey, ey);
            s_e[w][lane][1] = make_float4(ez, ez, ew, ew);
        }
        __syncwarp();

        // ---- inner: broadcast LDS + packed f32x2 FMA ----
#pragma unroll 4
        for (int j = 0; j < n; j++) {
            int off = s_off[w][j];
            const ulonglong2* ep = (const ulonglong2*)&s_e[w][j][0];
            ulonglong2 p0 = ep[0];       // (ex,ex),(ey,ey)
            ulonglong2 p1 = ep[1];       // (ez,ez),(ew,ew)
            unsigned long long xv = *(const unsigned long long*)(xl + off);
            asm("fma.rn.f32x2 %0, %1, %2, %0;" : "+l"(a0) : "l"(p0.x), "l"(xv));
            asm("fma.rn.f32x2 %0, %1, %2, %0;" : "+l"(a1) : "l"(p0.y), "l"(xv));
            asm("fma.rn.f32x2 %0, %1, %2, %0;" : "+l"(a2) : "l"(p1.x), "l"(xv));
            asm("fma.rn.f32x2 %0, %1, %2, %0;" : "+l"(a3) : "l"(p1.y), "l"(xv));
        }
        __syncwarp();
    }

    // rowsum reduce (xor-shfl -> all lanes hold totals)
#pragma unroll
    for (int o = 16; o > 0; o >>= 1) {
        e0 += __shfl_xor_sync(0xffffffffu, e0, o);
        e1 += __shfl_xor_sync(0xffffffffu, e1, o);
        e2 += __shfl_xor_sync(0xffffffffu, e2, o);
        e3 += __shfl_xor_sync(0xffffffffu, e3, o);
    }

    float i0 = 1.f / fmaxf(e0, 1e-12f);
    float i1 = 1.f / fmaxf(e1, 1e-12f);
    float i2 = 1.f / fmaxf(e2, 1e-12f);
    float i3 = 1.f / fmaxf(e3, 1e-12f);

    float2 bb = *(const float2*)(b + lane * 2);

    U64 A0, A1, A2, A3;
    A0.u = a0; A1.u = a1; A2.u = a2; A3.u = a3;

    float* o = out + (size_t)node * (NH * OUTD) + lane * 2;
    float2 r;
    r.x = elu1(A0.f.x * i0 + bb.x); r.y = elu1(A0.f.y * i0 + bb.y);
    *(float2*)(o + 0 * OUTD) = r;
    r.x = elu1(A1.f.x * i1 + bb.x); r.y = elu1(A1.f.y * i1 + bb.y);
    *(float2*)(o + 1 * OUTD) = r;
    r.x = elu1(A2.f.x * i2 + bb.x); r.y = elu1(A2.f.y * i2 + bb.y);
    *(float2*)(o + 2 * OUTD) = r;
    r.x = elu1(A3.f.x * i3 + bb.x); r.y = elu1(A3.f.y * i3 + bb.y);
    *(float2*)(o + 3 * OUTD) = r;
}

// ---------------- launch -----------------------------------------------------
extern "C" void kernel_launch(void* const* d_in, const int* in_sizes, int n_in,
                              void* d_out, int out_size)
{
    const float* h  = (const float*)d_in[0];   // [N, 256]
    const float* W  = (const float*)d_in[1];   // [256, 64]
    const float* Wl = (const float*)d_in[2];   // [4, 64]
    const float* Wr = (const float*)d_in[3];   // [4, 64]
    const float* b  = (const float*)d_in[4];   // [64]
    const int*   ei = (const int*)d_in[5];     // [2, E]
    float* out = (float*)d_out;

    int N = in_sizes[0] / IND;
    int E = in_sizes[5] / 2;

    int GB = (N + 127) / 128;
    int DEG_BLOCKS = 1024;
    k_fused1<<<GB + DEG_BLOCKS, 256>>>(h, W, ei, N, E, GB);

    k_scan<<<1, 1024>>>(N);

    int EB = (N + 7) / 8;
    int SB = (E + 255) / 256;
    k_fused3<<<EB + SB, 256>>>(Wl, Wr, ei, N, E, EB);

    k_agg<<<(N + 7) / 8, 256>>>(b, out, N);
}

// round 4
// speedup vs baseline: 1.1632x; 1.0597x over previous
#include <cuda_runtime.h>
#include <cuda_bf16.h>
#include <math.h>

#define NN 50000
#define EE 1600000
#define IND 256
#define OUTD 64
#define NH 4
typedef unsigned long long ull;

// ---------------- scratch (static device arrays; zero-initialized) ----------
__device__ float  g_x[NN * OUTD];          // 12.8 MB  x = h@W
__device__ float4 g_el[NN];
__device__ float4 g_er[NN];
__device__ int    g_deg[NN];               // invariant: zero at kernel_launch entry
__device__ int    g_off[NN + 1];
__device__ int    g_cur[NN];
__device__ int    g_dst_s[EE];             // CSR-sorted dst

// ---------------- helpers ----------------------------------------------------
#define L2E  1.4426950408889634f
#define L2E2 0.28853900817779268f   // 0.2 * log2(e)

__device__ __forceinline__ float lrelu_exp(float v)
{
    // exp(leaky_relu(v, 0.2)) = exp2(max(v,0)*log2e + min(v,0)*0.2*log2e)
    return exp2f(fmaxf(v, 0.f) * L2E + fminf(v, 0.f) * L2E2);
}
__device__ __forceinline__ float elu1(float v)
{
    return (v > 0.f) ? v : expm1f(v);
}

// ---------------- K1: fused [x = h@W]  ||  [degree histogram] ---------------
__global__ void k_fused1(const float* __restrict__ h, const float* __restrict__ W,
                         const int* __restrict__ ei, int N, int E, int gemm_blocks)
{
    __shared__ float  As2[32][132];     // k-major, m-contiguous, pad 132
    __shared__ float4 Bs[32 * 16];

    if (blockIdx.x >= gemm_blocks) {
        // ---- degree histogram (L2-atomic bound; overlaps gemm) ----
        int nb  = gridDim.x - gemm_blocks;
        int bid = blockIdx.x - gemm_blocks;
        int stride = nb * blockDim.x;
        const int4* e4 = (const int4*)ei;
        int E4 = E >> 2;
        for (int i = bid * blockDim.x + threadIdx.x; i < E4; i += stride) {
            int4 v = e4[i];
            atomicAdd(&g_deg[v.x], 1);
            atomicAdd(&g_deg[v.y], 1);
            atomicAdd(&g_deg[v.z], 1);
            atomicAdd(&g_deg[v.w], 1);
        }
        for (int e = (E & ~3) + bid * blockDim.x + threadIdx.x; e < E; e += stride)
            atomicAdd(&g_deg[ei[e]], 1);
        return;
    }

    // ---- GEMM path: 128x64 tile, 256 threads, 8x4 microtile ----
    const int tid = threadIdx.x;
    const int m0  = blockIdx.x * 128;
    const int tx  = tid & 15;
    const int ty  = tid >> 4;

    float acc[8][4];
#pragma unroll
    for (int i = 0; i < 8; i++)
#pragma unroll
        for (int j = 0; j < 4; j++) acc[i][j] = 0.f;

    for (int k0 = 0; k0 < IND; k0 += 32) {
#pragma unroll
        for (int l = 0; l < 4; l++) {
            int f   = tid + 256 * l;
            int row = f >> 3;
            int kq  = f & 7;
            int gm  = m0 + row;
            float4 v = make_float4(0.f, 0.f, 0.f, 0.f);
            if (gm < N) v = *(const float4*)(h + (size_t)gm * IND + k0 + kq * 4);
            As2[kq * 4 + 0][row] = v.x;
            As2[kq * 4 + 1][row] = v.y;
            As2[kq * 4 + 2][row] = v.z;
            As2[kq * 4 + 3][row] = v.w;
        }
#pragma unroll
        for (int l = 0; l < 2; l++) {
            int f  = tid + 256 * l;
            int kk = f >> 4;
            int nq = f & 15;
            Bs[kk * 16 + nq] = *(const float4*)(W + (size_t)(k0 + kk) * OUTD + nq * 4);
        }
        __syncthreads();

#pragma unroll
        for (int k = 0; k < 32; k++) {
            float4 a0 = *(const float4*)&As2[k][ty * 8];
            float4 a1 = *(const float4*)&As2[k][ty * 8 + 4];
            float4 bv = Bs[k * 16 + tx];
            float av[8] = {a0.x, a0.y, a0.z, a0.w, a1.x, a1.y, a1.z, a1.w};
#pragma unroll
            for (int i = 0; i < 8; i++) {
                acc[i][0] += av[i] * bv.x;
                acc[i][1] += av[i] * bv.y;
                acc[i][2] += av[i] * bv.z;
                acc[i][3] += av[i] * bv.w;
            }
        }
        __syncthreads();
    }

#pragma unroll
    for (int i = 0; i < 8; i++) {
        int gm = m0 + ty * 8 + i;
        if (gm < N) {
            float4 v = make_float4(acc[i][0], acc[i][1], acc[i][2], acc[i][3]);
            *(float4*)(g_x + (size_t)gm * OUTD + tx * 4) = v;
        }
    }
}

// ---------------- K2: fast exclusive scan + deg re-zero ----------------------
__global__ void k_scan(int N)
{
    __shared__ int sm[1024];
    const int t  = threadIdx.x;
    const int CH = (N + 1023) / 1024;
    int beg = t * CH;
    int end = beg + CH; if (end > N) end = N;

    int s = 0;
    for (int i = beg; i < end; i++) s += g_deg[i];
    sm[t] = s;
    __syncthreads();
#pragma unroll
    for (int o = 1; o < 1024; o <<= 1) {
        int v = (t >= o) ? sm[t - o] : 0;
        __syncthreads();
        sm[t] += v;
        __syncthreads();
    }
    int run = sm[t] - s;
    for (int i = beg; i < end; i++) {
        int dv = g_deg[i];
        g_off[i] = run;
        g_cur[i] = run;
        g_deg[i] = 0;
        run += dv;
    }
    if (t == 1023) g_off[N] = sm[1023];
}

// ---------------- K3: fused [el/er projections] || [CSR scatter (dst only)] --
__global__ void k_fused3(const float* __restrict__ Wl, const float* __restrict__ Wr,
                         const int* __restrict__ ei, int N, int E, int elr_blocks)
{
    if (blockIdx.x < elr_blocks) {
        int warp = (blockIdx.x * blockDim.x + threadIdx.x) >> 5;
        int lane = threadIdx.x & 31;
        if (warp >= N) return;

        const float* xr = g_x + (size_t)warp * OUTD;
        float x0 = xr[lane];
        float x1 = xr[lane + 32];

        float s[8];
#pragma unroll
        for (int hd = 0; hd < NH; hd++) {
            s[hd]     = x0 * __ldg(Wl + hd * OUTD + lane) + x1 * __ldg(Wl + hd * OUTD + lane + 32);
            s[4 + hd] = x0 * __ldg(Wr + hd * OUTD + lane) + x1 * __ldg(Wr + hd * OUTD + lane + 32);
        }
#pragma unroll
        for (int o = 16; o > 0; o >>= 1) {
#pragma unroll
            for (int j = 0; j < 8; j++) s[j] += __shfl_xor_sync(0xffffffffu, s[j], o);
        }
        if (lane == 0) {
            g_el[warp] = make_float4(s[0], s[1], s[2], s[3]);
            g_er[warp] = make_float4(s[4], s[5], s[6], s[7]);
        }
    } else {
        int e = (blockIdx.x - elr_blocks) * blockDim.x + threadIdx.x;
        if (e >= E) return;
        int sN = ei[e];
        int d  = ei[E + e];
        int pos = atomicAdd(&g_cur[sN], 1);
        g_dst_s[pos] = d;
    }
}

// ---------------- K4: per-node aggregation ----------------------------------
// 128 threads = 4 warps, warp per node. Double-buffered 32-edge chunks.
union U64 { ull u; float2 f; };

__global__ void __launch_bounds__(128) k_agg(const float* __restrict__ b,
                                             float* __restrict__ out, int N)
{
    __shared__ int    s_off[2][4][32];
    __shared__ float4 s_e[2][4][32][2];  // (ex,ex,ey,ey) , (ez,ez,ew,ew)

    const int w    = threadIdx.x >> 5;
    const int lane = threadIdx.x & 31;
    const int node = blockIdx.x * 4 + w;
    if (node >= N) return;

    const int s0 = g_off[node];
    const int s1 = g_off[node + 1];
    const float4 el = g_el[node];

    ull a0 = 0ull, a1 = 0ull, a2 = 0ull, a3 = 0ull;
    float e0 = 0.f, e1 = 0.f, e2 = 0.f, e3 = 0.f;

    const float* xl = g_x + lane * 2;   // lane owns dims {2*lane, 2*lane+1}

    // ---- stage one chunk into buffer `buf` (lane-parallel) ----
    auto stage = [&](int buf, int c, int n) {
        if (lane < n) {
            int d = g_dst_s[c + lane];
            float4 er = g_er[d];
            float ex = lrelu_exp(el.x + er.x);
            float ey = lrelu_exp(el.y + er.y);
            float ez = lrelu_exp(el.z + er.z);
            float ew = lrelu_exp(el.w + er.w);
            e0 += ex; e1 += ey; e2 += ez; e3 += ew;
            s_off[buf][w][lane]  = d * OUTD;
            s_e[buf][w][lane][0] = make_float4(ex, ex, ey, ey);
            s_e[buf][w][lane][1] = make_float4(ez, ez, ew, ew);
        }
    };

    // ---- consume a FULL chunk (n == 32): 8 fully-unrolled 4-edge batches ----
    auto consume32 = [&](int buf) {
#pragma unroll
        for (int g = 0; g < 8; g++) {
            int oo[4]; ull xx[4]; ulonglong2 pa[4], pb[4];
#pragma unroll
            for (int q = 0; q < 4; q++) oo[q] = s_off[buf][w][g * 4 + q];
#pragma unroll
            for (int q = 0; q < 4; q++) xx[q] = *(const ull*)(xl + oo[q]);
#pragma unroll
            for (int q = 0; q < 4; q++) {
                pa[q] = *(const ulonglong2*)&s_e[buf][w][g * 4 + q][0];
                pb[q] = *(const ulonglong2*)&s_e[buf][w][g * 4 + q][1];
            }
#pragma unroll
            for (int q = 0; q < 4; q++) {
                asm("fma.rn.f32x2 %0, %1, %2, %0;" : "+l"(a0) : "l"(pa[q].x), "l"(xx[q]));
                asm("fma.rn.f32x2 %0, %1, %2, %0;" : "+l"(a1) : "l"(pa[q].y), "l"(xx[q]));
                asm("fma.rn.f32x2 %0, %1, %2, %0;" : "+l"(a2) : "l"(pb[q].x), "l"(xx[q]));
                asm("fma.rn.f32x2 %0, %1, %2, %0;" : "+l"(a3) : "l"(pb[q].y), "l"(xx[q]));
            }
        }
    };

    // ---- consume a partial chunk ----
    auto consumeTail = [&](int buf, int n) {
        for (int j = 0; j < n; j++) {
            int off = s_off[buf][w][j];
            ulonglong2 p0 = *(const ulonglong2*)&s_e[buf][w][j][0];
            ulonglong2 p1 = *(const ulonglong2*)&s_e[buf][w][j][1];
            ull xv = *(const ull*)(xl + off);
            asm("fma.rn.f32x2 %0, %1, %2, %0;" : "+l"(a0) : "l"(p0.x), "l"(xv));
            asm("fma.rn.f32x2 %0, %1, %2, %0;" : "+l"(a1) : "l"(p0.y), "l"(xv));
            asm("fma.rn.f32x2 %0, %1, %2, %0;" : "+l"(a2) : "l"(p1.x), "l"(xv));
            asm("fma.rn.f32x2 %0, %1, %2, %0;" : "+l"(a3) : "l"(p1.y), "l"(xv));
        }
    };

    int c = s0;
    int buf = 0;
    int n0 = s1 - c; if (n0 > 32) n0 = 32;
    stage(0, c, n0);
    __syncwarp();

    while (c + 32 < s1) {
        // current chunk (at c, in buf) is full (32 edges)
        int cn = c + 32;
        int nn = s1 - cn; if (nn > 32) nn = 32;
        stage(buf ^ 1, cn, nn);     // prefetch next chunk (independent of consume)
        consume32(buf);
        __syncwarp();
        buf ^= 1;
        c = cn;
    }
    {
        int n = s1 - c;
        if (n == 32) consume32(buf);
        else if (n > 0) consumeTail(buf, n);
    }

    // rowsum reduce
#pragma unroll
    for (int o = 16; o > 0; o >>= 1) {
        e0 += __shfl_xor_sync(0xffffffffu, e0, o);
        e1 += __shfl_xor_sync(0xffffffffu, e1, o);
        e2 += __shfl_xor_sync(0xffffffffu, e2, o);
        e3 += __shfl_xor_sync(0xffffffffu, e3, o);
    }

    float i0 = 1.f / fmaxf(e0, 1e-12f);
    float i1 = 1.f / fmaxf(e1, 1e-12f);
    float i2 = 1.f / fmaxf(e2, 1e-12f);
    float i3 = 1.f / fmaxf(e3, 1e-12f);

    float2 bb = *(const float2*)(b + lane * 2);

    U64 A0, A1, A2, A3;
    A0.u = a0; A1.u = a1; A2.u = a2; A3.u = a3;

    float* o = out + (size_t)node * (NH * OUTD) + lane * 2;
    float2 r;
    r.x = elu1(A0.f.x * i0 + bb.x); r.y = elu1(A0.f.y * i0 + bb.y);
    *(float2*)(o + 0 * OUTD) = r;
    r.x = elu1(A1.f.x * i1 + bb.x); r.y = elu1(A1.f.y * i1 + bb.y);
    *(float2*)(o + 1 * OUTD) = r;
    r.x = elu1(A2.f.x * i2 + bb.x); r.y = elu1(A2.f.y * i2 + bb.y);
    *(float2*)(o + 2 * OUTD) = r;
    r.x = elu1(A3.f.x * i3 + bb.x); r.y = elu1(A3.f.y * i3 + bb.y);
    *(float2*)(o + 3 * OUTD) = r;
}

// ---------------- launch -----------------------------------------------------
extern "C" void kernel_launch(void* const* d_in, const int* in_sizes, int n_in,
                              void* d_out, int out_size)
{
    const float* h  = (const float*)d_in[0];   // [N, 256]
    const float* W  = (const float*)d_in[1];   // [256, 64]
    const float* Wl = (const float*)d_in[2];   // [4, 64]
    const float* Wr = (const float*)d_in[3];   // [4, 64]
    const float* b  = (const float*)d_in[4];   // [64]
    const int*   ei = (const int*)d_in[5];     // [2, E]
    float* out = (float*)d_out;

    int N = in_sizes[0] / IND;
    int E = in_sizes[5] / 2;

    int GB = (N + 127) / 128;
    int DEG_BLOCKS = 512;
    k_fused1<<<GB + DEG_BLOCKS, 256>>>(h, W, ei, N, E, GB);

    k_scan<<<1, 1024>>>(N);

    int EB = (N + 7) / 8;
    int SB = (E + 255) / 256;
    k_fused3<<<EB + SB, 256>>>(Wl, Wr, ei, N, E, EB);

    k_agg<<<(N + 3) / 4, 128>>>(b, out, N);
}

// round 5
// speedup vs baseline: 1.3837x; 1.1896x over previous
#include <cuda_runtime.h>
#include <cuda_bf16.h>
#include <math.h>

#define NN 50000
#define EE 1600000
#define IND 256
#define OUTD 64
#define NH 4
typedef unsigned long long ull;

// ---------------- scratch (static device arrays; zero-initialized) ----------
__device__ float  g_x[NN * OUTD];          // 12.8 MB  x = h@W
__device__ float4 g_el[NN];
__device__ float4 g_er[NN];
__device__ int    g_deg[NN];               // invariant: zero at kernel_launch entry
__device__ int    g_off[NN + 1];
__device__ int    g_cur[NN];
__device__ int    g_dst_s[EE];             // CSR-sorted dst

// ---------------- helpers ----------------------------------------------------
#define L2E  1.4426950408889634f
#define L2E2 0.28853900817779268f   // 0.2 * log2(e)

__device__ __forceinline__ float lrelu_exp(float v)
{
    return exp2f(fmaxf(v, 0.f) * L2E + fminf(v, 0.f) * L2E2);
}
__device__ __forceinline__ float elu1(float v)
{
    return (v > 0.f) ? v : expm1f(v);
}
__device__ __forceinline__ ull dup2(float v)
{
    ull r; asm("mov.b64 %0, {%1, %1};" : "=l"(r) : "f"(v)); return r;
}
union U64 { ull u; float2 f; };

// ---------------- K1: x = h @ W  (f32x2 inner loop) --------------------------
// 128x64 tile, 256 threads, 8x4 microtile; rows paired into f32x2 lanes.
__global__ void k_gemm(const float* __restrict__ h, const float* __restrict__ W, int N)
{
    __shared__ float  As2[32][132];     // k-major, m-contiguous, pad 132
    __shared__ float4 Bs[32 * 16];

    const int tid = threadIdx.x;
    const int m0  = blockIdx.x * 128;
    const int tx  = tid & 15;
    const int ty  = tid >> 4;

    // acc2[r][j]: packed (row 2r, row 2r+1) for output col tx*4+j
    ull acc2[4][4];
#pragma unroll
    for (int r = 0; r < 4; r++)
#pragma unroll
        for (int j = 0; j < 4; j++) acc2[r][j] = 0ull;

    for (int k0 = 0; k0 < IND; k0 += 32) {
#pragma unroll
        for (int l = 0; l < 4; l++) {
            int f   = tid + 256 * l;
            int row = f >> 3;
            int kq  = f & 7;
            int gm  = m0 + row;
            float4 v = make_float4(0.f, 0.f, 0.f, 0.f);
            if (gm < N) v = *(const float4*)(h + (size_t)gm * IND + k0 + kq * 4);
            As2[kq * 4 + 0][row] = v.x;
            As2[kq * 4 + 1][row] = v.y;
            As2[kq * 4 + 2][row] = v.z;
            As2[kq * 4 + 3][row] = v.w;
        }
#pragma unroll
        for (int l = 0; l < 2; l++) {
            int f  = tid + 256 * l;
            int kk = f >> 4;
            int nq = f & 15;
            Bs[kk * 16 + nq] = *(const float4*)(W + (size_t)(k0 + kk) * OUTD + nq * 4);
        }
        __syncthreads();

#pragma unroll
        for (int k = 0; k < 32; k++) {
            // A row-pairs: 8 consecutive rows as 4 packed ulls (8B-aligned)
            const ull* ap = (const ull*)&As2[k][ty * 8];
            ull a[4] = {ap[0], ap[1], ap[2], ap[3]};
            float4 bv = Bs[k * 16 + tx];
            ull b0 = dup2(bv.x), b1 = dup2(bv.y), b2 = dup2(bv.z), b3 = dup2(bv.w);
#pragma unroll
            for (int r = 0; r < 4; r++) {
                asm("fma.rn.f32x2 %0, %1, %2, %0;" : "+l"(acc2[r][0]) : "l"(a[r]), "l"(b0));
                asm("fma.rn.f32x2 %0, %1, %2, %0;" : "+l"(acc2[r][1]) : "l"(a[r]), "l"(b1));
                asm("fma.rn.f32x2 %0, %1, %2, %0;" : "+l"(acc2[r][2]) : "l"(a[r]), "l"(b2));
                asm("fma.rn.f32x2 %0, %1, %2, %0;" : "+l"(acc2[r][3]) : "l"(a[r]), "l"(b3));
            }
        }
        __syncthreads();
    }

#pragma unroll
    for (int r = 0; r < 4; r++) {
        int gm0 = m0 + ty * 8 + 2 * r;
        U64 t0, t1, t2, t3;
        t0.u = acc2[r][0]; t1.u = acc2[r][1]; t2.u = acc2[r][2]; t3.u = acc2[r][3];
        if (gm0 < N)
            *(float4*)(g_x + (size_t)gm0 * OUTD + tx * 4) =
                make_float4(t0.f.x, t1.f.x, t2.f.x, t3.f.x);
        if (gm0 + 1 < N)
            *(float4*)(g_x + (size_t)(gm0 + 1) * OUTD + tx * 4) =
                make_float4(t0.f.y, t1.f.y, t2.f.y, t3.f.y);
    }
}

// ---------------- K2: degree histogram ---------------------------------------
__global__ void k_deg(const int* __restrict__ ei, int E)
{
    int stride = gridDim.x * blockDim.x;
    const int4* e4 = (const int4*)ei;
    int E4 = E >> 2;
    for (int i = blockIdx.x * blockDim.x + threadIdx.x; i < E4; i += stride) {
        int4 v = e4[i];
        atomicAdd(&g_deg[v.x], 1);
        atomicAdd(&g_deg[v.y], 1);
        atomicAdd(&g_deg[v.z], 1);
        atomicAdd(&g_deg[v.w], 1);
    }
    for (int e = (E & ~3) + blockIdx.x * blockDim.x + threadIdx.x; e < E; e += stride)
        atomicAdd(&g_deg[ei[e]], 1);
}

// ---------------- K3: exclusive scan + deg re-zero ---------------------------
__global__ void k_scan(int N)
{
    __shared__ int sm[1024];
    const int t  = threadIdx.x;
    const int CH = (N + 1023) / 1024;
    int beg = t * CH;
    int end = beg + CH; if (end > N) end = N;

    int s = 0;
    for (int i = beg; i < end; i++) s += g_deg[i];
    sm[t] = s;
    __syncthreads();
#pragma unroll
    for (int o = 1; o < 1024; o <<= 1) {
        int v = (t >= o) ? sm[t - o] : 0;
        __syncthreads();
        sm[t] += v;
        __syncthreads();
    }
    int run = sm[t] - s;
    for (int i = beg; i < end; i++) {
        int dv = g_deg[i];
        g_off[i] = run;
        g_cur[i] = run;
        g_deg[i] = 0;
        run += dv;
    }
    if (t == 1023) g_off[N] = sm[1023];
}

// ---------------- K4: CSR scatter (dst only), 4 edges/thread -----------------
__global__ void k_scatter(const int* __restrict__ ei, int E)
{
    int i = blockIdx.x * blockDim.x + threadIdx.x;
    int e = i * 4;
    if (((E & 3) == 0) && (e + 4 <= E)) {
        int4 s4 = *(const int4*)(ei + e);
        int4 d4 = *(const int4*)(ei + E + e);
        g_dst_s[atomicAdd(&g_cur[s4.x], 1)] = d4.x;
        g_dst_s[atomicAdd(&g_cur[s4.y], 1)] = d4.y;
        g_dst_s[atomicAdd(&g_cur[s4.z], 1)] = d4.z;
        g_dst_s[atomicAdd(&g_cur[s4.w], 1)] = d4.w;
    } else {
        for (int q = e; q < E && q < e + 4; q++) {
            int s = ei[q];
            int d = ei[E + q];
            g_dst_s[atomicAdd(&g_cur[s], 1)] = d;
        }
    }
}

// ---------------- K5: el/er projections (warp per node) ----------------------
__global__ void k_elr(const float* __restrict__ Wl, const float* __restrict__ Wr, int N)
{
    int warp = (blockIdx.x * blockDim.x + threadIdx.x) >> 5;
    int lane = threadIdx.x & 31;
    if (warp >= N) return;

    const float* xr = g_x + (size_t)warp * OUTD;
    float x0 = xr[lane];
    float x1 = xr[lane + 32];

    float s[8];
#pragma unroll
    for (int hd = 0; hd < NH; hd++) {
        s[hd]     = x0 * __ldg(Wl + hd * OUTD + lane) + x1 * __ldg(Wl + hd * OUTD + lane + 32);
        s[4 + hd] = x0 * __ldg(Wr + hd * OUTD + lane) + x1 * __ldg(Wr + hd * OUTD + lane + 32);
    }
#pragma unroll
    for (int o = 16; o > 0; o >>= 1) {
#pragma unroll
        for (int j = 0; j < 8; j++) s[j] += __shfl_xor_sync(0xffffffffu, s[j], o);
    }
    if (lane == 0) {
        g_el[warp] = make_float4(s[0], s[1], s[2], s[3]);
        g_er[warp] = make_float4(s[4], s[5], s[6], s[7]);
    }
}

// ---------------- K6: per-node aggregation (unchanged from round 4) ----------
__global__ void __launch_bounds__(128) k_agg(const float* __restrict__ b,
                                             float* __restrict__ out, int N)
{
    __shared__ int    s_off[2][4][32];
    __shared__ float4 s_e[2][4][32][2];

    const int w    = threadIdx.x >> 5;
    const int lane = threadIdx.x & 31;
    const int node = blockIdx.x * 4 + w;
    if (node >= N) return;

    const int s0 = g_off[node];
    const int s1 = g_off[node + 1];
    const float4 el = g_el[node];

    ull a0 = 0ull, a1 = 0ull, a2 = 0ull, a3 = 0ull;
    float e0 = 0.f, e1 = 0.f, e2 = 0.f, e3 = 0.f;

    const float* xl = g_x + lane * 2;

    auto stage = [&](int buf, int c, int n) {
        if (lane < n) {
            int d = g_dst_s[c + lane];
            float4 er = g_er[d];
            float ex = lrelu_exp(el.x + er.x);
            float ey = lrelu_exp(el.y + er.y);
            float ez = lrelu_exp(el.z + er.z);
            float ew = lrelu_exp(el.w + er.w);
            e0 += ex; e1 += ey; e2 += ez; e3 += ew;
            s_off[buf][w][lane]  = d * OUTD;
            s_e[buf][w][lane][0] = make_float4(ex, ex, ey, ey);
            s_e[buf][w][lane][1] = make_float4(ez, ez, ew, ew);
        }
    };

    auto consume32 = [&](int buf) {
#pragma unroll
        for (int g = 0; g < 8; g++) {
            int oo[4]; ull xx[4]; ulonglong2 pa[4], pb[4];
#pragma unroll
            for (int q = 0; q < 4; q++) oo[q] = s_off[buf][w][g * 4 + q];
#pragma unroll
            for (int q = 0; q < 4; q++) xx[q] = *(const ull*)(xl + oo[q]);
#pragma unroll
            for (int q = 0; q < 4; q++) {
                pa[q] = *(const ulonglong2*)&s_e[buf][w][g * 4 + q][0];
                pb[q] = *(const ulonglong2*)&s_e[buf][w][g * 4 + q][1];
            }
#pragma unroll
            for (int q = 0; q < 4; q++) {
                asm("fma.rn.f32x2 %0, %1, %2, %0;" : "+l"(a0) : "l"(pa[q].x), "l"(xx[q]));
                asm("fma.rn.f32x2 %0, %1, %2, %0;" : "+l"(a1) : "l"(pa[q].y), "l"(xx[q]));
                asm("fma.rn.f32x2 %0, %1, %2, %0;" : "+l"(a2) : "l"(pb[q].x), "l"(xx[q]));
                asm("fma.rn.f32x2 %0, %1, %2, %0;" : "+l"(a3) : "l"(pb[q].y), "l"(xx[q]));
            }
        }
    };

    auto consumeTail = [&](int buf, int n) {
        for (int j = 0; j < n; j++) {
            int off = s_off[buf][w][j];
            ulonglong2 p0 = *(const ulonglong2*)&s_e[buf][w][j][0];
            ulonglong2 p1 = *(const ulonglong2*)&s_e[buf][w][j][1];
            ull xv = *(const ull*)(xl + off);
            asm("fma.rn.f32x2 %0, %1, %2, %0;" : "+l"(a0) : "l"(p0.x), "l"(xv));
            asm("fma.rn.f32x2 %0, %1, %2, %0;" : "+l"(a1) : "l"(p0.y), "l"(xv));
            asm("fma.rn.f32x2 %0, %1, %2, %0;" : "+l"(a2) : "l"(p1.x), "l"(xv));
            asm("fma.rn.f32x2 %0, %1, %2, %0;" : "+l"(a3) : "l"(p1.y), "l"(xv));
        }
    };

    int c = s0;
    int buf = 0;
    int n0 = s1 - c; if (n0 > 32) n0 = 32;
    stage(0, c, n0);
    __syncwarp();

    while (c + 32 < s1) {
        int cn = c + 32;
        int nn = s1 - cn; if (nn > 32) nn = 32;
        stage(buf ^ 1, cn, nn);
        consume32(buf);
        __syncwarp();
        buf ^= 1;
        c = cn;
    }
    {
        int n = s1 - c;
        if (n == 32) consume32(buf);
        else if (n > 0) consumeTail(buf, n);
    }

#pragma unroll
    for (int o = 16; o > 0; o >>= 1) {
        e0 += __shfl_xor_sync(0xffffffffu, e0, o);
        e1 += __shfl_xor_sync(0xffffffffu, e1, o);
        e2 += __shfl_xor_sync(0xffffffffu, e2, o);
        e3 += __shfl_xor_sync(0xffffffffu, e3, o);
    }

    float i0 = 1.f / fmaxf(e0, 1e-12f);
    float i1 = 1.f / fmaxf(e1, 1e-12f);
    float i2 = 1.f / fmaxf(e2, 1e-12f);
    float i3 = 1.f / fmaxf(e3, 1e-12f);

    float2 bb = *(const float2*)(b + lane * 2);

    U64 A0, A1, A2, A3;
    A0.u = a0; A1.u = a1; A2.u = a2; A3.u = a3;

    float* o = out + (size_t)node * (NH * OUTD) + lane * 2;
    float2 r;
    r.x = elu1(A0.f.x * i0 + bb.x); r.y = elu1(A0.f.y * i0 + bb.y);
    *(float2*)(o + 0 * OUTD) = r;
    r.x = elu1(A1.f.x * i1 + bb.x); r.y = elu1(A1.f.y * i1 + bb.y);
    *(float2*)(o + 1 * OUTD) = r;
    r.x = elu1(A2.f.x * i2 + bb.x); r.y = elu1(A2.f.y * i2 + bb.y);
    *(float2*)(o + 2 * OUTD) = r;
    r.x = elu1(A3.f.x * i3 + bb.x); r.y = elu1(A3.f.y * i3 + bb.y);
    *(float2*)(o + 3 * OUTD) = r;
}

// ---------------- launch: fork-join two-stream graph --------------------------
extern "C" void kernel_launch(void* const* d_in, const int* in_sizes, int n_in,
                              void* d_out, int out_size)
{
    const float* h  = (const float*)d_in[0];   // [N, 256]
    const float* W  = (const float*)d_in[1];   // [256, 64]
    const float* Wl = (const float*)d_in[2];   // [4, 64]
    const float* Wr = (const float*)d_in[3];   // [4, 64]
    const float* b  = (const float*)d_in[4];   // [64]
    const int*   ei = (const int*)d_in[5];     // [2, E]
    float* out = (float*)d_out;

    int N = in_sizes[0] / IND;
    int E = in_sizes[5] / 2;

    // one-time infra (streams/events are reused; the captured WORK is
    // identical on every call — deterministic)
    static cudaStream_t s1 = nullptr;
    static cudaEvent_t  evFork = nullptr, evJoin = nullptr;
    if (s1 == nullptr) {
        cudaStreamCreateWithFlags(&s1, cudaStreamNonBlocking);
        cudaEventCreateWithFlags(&evFork, cudaEventDisableTiming);
        cudaEventCreateWithFlags(&evJoin, cudaEventDisableTiming);
    }

    // fork: s1 handles the CSR-build chain (independent of the GEMM)
    cudaEventRecord(evFork, 0);
    cudaStreamWaitEvent(s1, evFork, 0);

    k_deg<<<512, 256, 0, s1>>>(ei, E);
    k_scan<<<1, 1024, 0, s1>>>(N);
    int SB = ((E + 3) / 4 + 255) / 256;
    k_scatter<<<SB, 256, 0, s1>>>(ei, E);
    cudaEventRecord(evJoin, s1);

    // main stream: gemm -> elr
    k_gemm<<<(N + 127) / 128, 256>>>(h, W, N);
    k_elr<<<(N + 7) / 8, 256>>>(Wl, Wr, N);

    // join: agg needs CSR (s1) + el/er (main)
    cudaStreamWaitEvent(0, evJoin, 0);
    k_agg<<<(N + 3) / 4, 128>>>(b, out, N);
}